// round 17
// baseline (speedup 1.0000x reference)
#include <cuda_runtime.h>
#include <cuda_bf16.h>
#include <mma.h>
#include <cstdint>

#define HOP   256
#define KUP   800
#define NMEL  80
#define RC    120
#define SC    240
#define NQ    256
#define NB    16
#define MAXL  40960
#define TT    128
#define NTH   512

// ---------------- scratch (device globals; sanctioned) --------------------------
static __device__ float g_cond[NMEL * MAXL];
static __device__ float g_res0[RC * MAXL];
static __device__ float g_res1[RC * MAXL];
static __device__ float g_skip[SC * MAXL];
static __device__ float g_y[NQ * MAXL];
static __device__ float2 g_dpk1[128 * 240];
static __device__ float2 g_dpk2[128 * 256];
// bf16 hi/lo weight planes, row-major
static __device__ __nv_bfloat16 g_wAh[NB * 240 * 320];
static __device__ __nv_bfloat16 g_wAl[NB * 240 * 320];
static __device__ __nv_bfloat16 g_wBh[NB * 368 * 128];
static __device__ __nv_bfloat16 g_wBl[NB * 368 * 128];

typedef unsigned long long ull;

// ---------------- f32x2 helpers (dense head) ------------------------------------
__device__ __forceinline__ ull pk2(float x, float y) {
    ull r; asm("mov.b64 %0, {%1,%2};" : "=l"(r) : "f"(x), "f"(y)); return r;
}
__device__ __forceinline__ ull fma2(ull a, ull b, ull c) {
    ull d; asm("fma.rn.f32x2 %0, %1, %2, %3;" : "=l"(d) : "l"(a), "l"(b), "l"(c)); return d;
}
__device__ __forceinline__ float2 up2(ull v) {
    float2 f; asm("mov.b64 {%0,%1}, %2;" : "=f"(f.x), "=f"(f.y) : "l"(v)); return f;
}
__device__ __forceinline__ void splat4(ull* dst, const float* base) {
    float4 v = *(const float4*)base;
    dst[0] = pk2(v.x, v.x); dst[1] = pk2(v.y, v.y);
    dst[2] = pk2(v.z, v.z); dst[3] = pk2(v.w, v.w);
}
__device__ __forceinline__ void halfS(ull z[4][4], const float* sX,
                                      int cc, int tl, const ulonglong2* w) {
    ull C[4];
    splat4(C, &sX[cc * TT + tl]);
    #pragma unroll
    for (int j = 0; j < 4; j++)
        #pragma unroll
        for (int k = 0; k < 4; k++) z[j][k] = fma2(w[j].x, C[k], z[j][k]);
    splat4(C, &sX[(cc + 1) * TT + tl]);
    #pragma unroll
    for (int j = 0; j < 4; j++)
        #pragma unroll
        for (int k = 0; k < 4; k++) z[j][k] = fma2(w[j].y, C[k], z[j][k]);
}

// ---------------- prepack: bf16 hi/lo weight planes -----------------------------
__global__ void prepack_wmma(const float* __restrict__ bcw, const float* __restrict__ bqw,
                             const float* __restrict__ bsw, const float* __restrict__ brw,
                             __nv_bfloat16* __restrict__ wAh, __nv_bfloat16* __restrict__ wAl,
                             __nv_bfloat16* __restrict__ wBh, __nv_bfloat16* __restrict__ wBl) {
    int idx = blockIdx.x * blockDim.x + threadIdx.x;
    const int NAtot = NB * 240 * 320;
    const int NBtot = NB * 368 * 128;
    if (idx < NAtot) {
        int i = idx / 76800;
        int r = (idx / 320) % 240;
        int k = idx % 320;
        const float* cw = bcw + (size_t)i * SC * RC * 2;
        const float* qw = bqw + (size_t)i * SC * NMEL;
        float v;
        if (k < 120) v = cw[(r * RC + k) * 2];
        else if (k < 240) v = cw[(r * RC + (k - 120)) * 2 + 1];
        else v = qw[r * NMEL + (k - 240)];
        __nv_bfloat16 h = __float2bfloat16_rn(v);
        wAh[idx] = h;
        wAl[idx] = __float2bfloat16_rn(v - __bfloat162float(h));
    } else if (idx < NAtot + NBtot) {
        int t = idx - NAtot;
        int i = t / 47104;
        int r = (t / 128) % 368;
        int k = t % 128;
        float v = 0.f;
        if (k < 120) {
            if (r < 240) v = bsw[(size_t)i * SC * RC + r * RC + k];
            else if (r < 360) v = brw[(size_t)i * RC * RC + (r - 240) * RC + k];
        }
        __nv_bfloat16 h = __float2bfloat16_rn(v);
        wBh[t] = h;
        wBl[t] = __float2bfloat16_rn(v - __bfloat162float(h));
    }
}

__global__ void prepack_dense(const float* __restrict__ h1w, const float* __restrict__ h2w,
                              float2* __restrict__ dpk1, float2* __restrict__ dpk2) {
    int idx = blockIdx.x * blockDim.x + threadIdx.x;
    const int D1 = 128 * 240, D2 = 128 * 256;
    if (idx < D1) {
        int p = idx / 240, c = idx % 240;
        dpk1[p * 240 + c] = make_float2(h1w[(2 * p) * SC + c], h1w[(2 * p + 1) * SC + c]);
    } else if (idx < D1 + D2) {
        int k = idx - D1;
        int p = k / 256, c = k % 256;
        dpk2[p * 256 + c] = make_float2(h2w[(2 * p) * NQ + c], h2w[(2 * p + 1) * NQ + c]);
    }
}

// ---------------- cond upsampling (unchanged, passing) --------------------------
__global__ __launch_bounds__(256, 1)
void cond_kernel(const float* __restrict__ mel, const float* __restrict__ upw,
                 const float* __restrict__ upb, float* __restrict__ cond,
                 int L, int Tmel) {
    extern __shared__ float sm[];
    const int MS = Tmel + 8;
    float* smel = sm;
    float* sw = sm + NMEL * MS;
    int tid = threadIdx.x;
    int p = blockIdx.x;
    int k0 = 255 - p;
    for (int idx = tid; idx < NMEL * MS; idx += 256) {
        int c = idx / MS, col = idx - c * MS;
        smel[idx] = (col < Tmel) ? mel[c * Tmel + col] : 0.f;
    }
    for (int idx = tid; idx < NMEL * NMEL * 4; idx += 256) {
        int j = idx & 3, oc = idx >> 2;
        int k = k0 + 256 * j;
        sw[idx] = (k < KUP) ? upw[oc * KUP + k] : 0.f;
    }
    __syncthreads();
    int nI = (L - p + 255) >> 8;
    int tx = tid & 7, gy = tid >> 3;
    for (int o = gy; o < NMEL; o += 32) {
        float b = upb[o];
        for (int ib = 0; ib < nI; ib += 32) {
            int i0 = ib + tx * 4;
            float a0 = b, a1 = b, a2 = b, a3 = b;
            for (int c = 0; c < NMEL; c++) {
                const float4 w = *(const float4*)&sw[(o * NMEL + c) << 2];
                const float* mp = &smel[c * MS + i0 + 1];
                float m0 = mp[0], m1 = mp[1], m2 = mp[2], m3 = mp[3];
                float m4 = mp[4], m5 = mp[5], m6 = mp[6];
                a0 += w.x * m0 + w.y * m1 + w.z * m2 + w.w * m3;
                a1 += w.x * m1 + w.y * m2 + w.z * m3 + w.w * m4;
                a2 += w.x * m2 + w.y * m3 + w.z * m4 + w.w * m5;
                a3 += w.x * m3 + w.y * m4 + w.z * m5 + w.w * m6;
            }
            int t = p + (i0 << 8);
            if (i0     < nI) cond[o * L + t]       = a0;
            if (i0 + 1 < nI) cond[o * L + t + 256] = a1;
            if (i0 + 2 < nI) cond[o * L + t + 512] = a2;
            if (i0 + 3 < nI) cond[o * L + t + 768] = a3;
        }
    }
}

__global__ void init_kernel(const float* __restrict__ wav, const float* __restrict__ inw,
                            const float* __restrict__ inb, float* __restrict__ res, int L) {
    int idx = blockIdx.x * blockDim.x + threadIdx.x;
    if (idx >= RC * L) return;
    int c = idx / L, t = idx - c * L;
    res[idx] = inw[c] * wav[t] + inb[c];
}

// ---------------- wmma (HMMA bf16) WaveNet block --------------------------------
// SMEM map (bytes):
//  XH 0..87040     [320][136] bf16
//  XL 87040..174080
//  WH 174080..191744  [368][24] bf16 staged chunk
//  WL 191744..209408
// Overlays after phase A:  Z fp32 [240][136] at 0 (130560);
//  Hh [128][136] bf16 at 0 (34816); Hl at 34816; ZB fp32 [192][136] at 69632.
#define SM_XL  87040
#define SM_WH  174080
#define SM_WL  191744
#define SM_HL  34816
#define SM_ZB  69632
#define SMEM_BLK 209408
#define XS 136
#define WS 24

__global__ __launch_bounds__(NTH, 1)
void block_wmma(const float* __restrict__ rin, float* __restrict__ rout,
                float* __restrict__ skip, const float* __restrict__ condp,
                const __nv_bfloat16* __restrict__ wAh, const __nv_bfloat16* __restrict__ wAl,
                const __nv_bfloat16* __restrict__ wBh, const __nv_bfloat16* __restrict__ wBl,
                const float* __restrict__ cb, const float* __restrict__ qb,
                const float* __restrict__ sbv, const float* __restrict__ rb,
                int d, int L, int first, int wres) {
    using namespace nvcuda;
    extern __shared__ unsigned char smem[];
    __nv_bfloat16* sXh = (__nv_bfloat16*)smem;
    __nv_bfloat16* sXl = (__nv_bfloat16*)(smem + SM_XL);
    __nv_bfloat16* sWh = (__nv_bfloat16*)(smem + SM_WH);
    __nv_bfloat16* sWl = (__nv_bfloat16*)(smem + SM_WL);

    int tid = threadIdx.x;
    int wid = tid >> 5;
    int t0 = blockIdx.x * 128;
    const int n = wid & 7;       // n-tile (16 t cols)
    const int half = wid >> 3;   // m-tile parity

    // ---- build X bf16 hi/lo ----
    for (int idx = tid; idx < 320 * 128; idx += NTH) {
        int k = idx >> 7, t = idx & 127;
        int tg = t0 + t;
        float v = 0.f;
        if (tg < L) {
            if (k < 120) { int ta = tg - d; if (ta >= 0) v = rin[k * L + ta]; }
            else if (k < 240) v = rin[(k - 120) * L + tg];
            else v = condp[(k - 240) * L + tg];
        }
        __nv_bfloat16 bh = __float2bfloat16_rn(v);
        sXh[k * XS + t] = bh;
        sXl[k * XS + t] = __float2bfloat16_rn(v - __bfloat162float(bh));
    }
    __syncthreads();

    typedef wmma::fragment<wmma::matrix_a, 16, 16, 16, __nv_bfloat16, wmma::row_major> FragA;
    typedef wmma::fragment<wmma::matrix_b, 16, 16, 16, __nv_bfloat16, wmma::row_major> FragB;
    typedef wmma::fragment<wmma::accumulator, 16, 16, 16, float> FragC;

    // ---- Phase A: Z[240][128] = W_A[240][320] * X ----
    {
        FragC acc[8];
        const int nt = 8 - half;  // half=0: m 0,2..14 (8); half=1: m 1,3..13 (7)
        #pragma unroll
        for (int j = 0; j < 8; j++) if (j < nt) wmma::fill_fragment(acc[j], 0.f);

        for (int ch = 0; ch < 20; ch++) {
            // stage W chunk [240][16] hi+lo
            const uint4* gah = (const uint4*)wAh;
            const uint4* gal = (const uint4*)wAl;
            uint4* dh = (uint4*)sWh;
            uint4* dl = (uint4*)sWl;
            for (int j2 = tid; j2 < 480; j2 += NTH) {
                int m = j2 >> 1, c2 = j2 & 1;
                dh[m * 3 + c2] = gah[m * 40 + ch * 2 + c2];
                dl[m * 3 + c2] = gal[m * 40 + ch * 2 + c2];
            }
            __syncthreads();
            FragB bh, bl;
            wmma::load_matrix_sync(bh, sXh + ch * 16 * XS + n * 16, XS);
            wmma::load_matrix_sync(bl, sXl + ch * 16 * XS + n * 16, XS);
            #pragma unroll
            for (int j = 0; j < 8; j++) {
                if (j < nt) {
                    int mt = half + 2 * j;
                    FragA ah, al;
                    wmma::load_matrix_sync(ah, sWh + mt * 16 * WS, WS);
                    wmma::load_matrix_sync(al, sWl + mt * 16 * WS, WS);
                    wmma::mma_sync(acc[j], ah, bh, acc[j]);
                    wmma::mma_sync(acc[j], al, bh, acc[j]);
                    wmma::mma_sync(acc[j], ah, bl, acc[j]);
                }
            }
            __syncthreads();
        }
        // store Z fp32 over X region (X dead)
        float* Z = (float*)smem;
        #pragma unroll
        for (int j = 0; j < 8; j++) {
            if (j < nt) {
                int mt = half + 2 * j;
                wmma::store_matrix_sync(Z + mt * 16 * XS + n * 16, acc[j], XS, wmma::mem_row_major);
            }
        }
    }
    __syncthreads();

    // ---- gate: h = tanh(zt+b) * sigmoid(zs+b); keep in regs, then write bf16 H ----
    float hv[30];
    {
        const float* Z = (const float*)smem;
        #pragma unroll
        for (int j = 0; j < 30; j++) {
            int f = tid + j * NTH;
            int k = f >> 7, t = f & 127;
            float a = Z[k * XS + t] + cb[k] + qb[k];
            float s = Z[(k + 120) * XS + t] + cb[k + 120] + qb[k + 120];
            hv[j] = tanhf(a) * (1.f / (1.f + __expf(-s)));
        }
    }
    __syncthreads();
    {
        __nv_bfloat16* Hh = (__nv_bfloat16*)smem;
        __nv_bfloat16* Hl = (__nv_bfloat16*)(smem + SM_HL);
        #pragma unroll
        for (int j = 0; j < 30; j++) {
            int f = tid + j * NTH;
            int k = f >> 7, t = f & 127;
            __nv_bfloat16 bh = __float2bfloat16_rn(hv[j]);
            Hh[k * XS + t] = bh;
            Hl[k * XS + t] = __float2bfloat16_rn(hv[j] - __bfloat162float(bh));
        }
        // zero pad rows 120..127
        for (int idx = tid; idx < 8 * 128; idx += NTH) {
            int r = 120 + (idx >> 7), t = idx & 127;
            Hh[r * XS + t] = __float2bfloat16_rn(0.f);
            Hl[r * XS + t] = __float2bfloat16_rn(0.f);
        }
    }
    __syncthreads();

    // ---- Phase B: [368][128] * H, 2 M-passes ----
    const __nv_bfloat16* Hh = (const __nv_bfloat16*)smem;
    const __nv_bfloat16* Hl = (const __nv_bfloat16*)(smem + SM_HL);
    for (int pass = 0; pass < 2; pass++) {
        FragC accb[6];
        bool val[6];
        int mts[6];
        #pragma unroll
        for (int j = 0; j < 6; j++) {
            int mt = pass * 12 + half + 2 * j;
            mts[j] = mt;
            val[j] = (pass == 0) ? (mt < 12) : (mt < 23);
            if (val[j]) wmma::fill_fragment(accb[j], 0.f);
        }
        for (int ch = 0; ch < 8; ch++) {
            const uint4* gbh = (const uint4*)wBh;
            const uint4* gbl = (const uint4*)wBl;
            uint4* dh = (uint4*)sWh;
            uint4* dl = (uint4*)sWl;
            for (int j2 = tid; j2 < 736; j2 += NTH) {
                int m = j2 >> 1, c2 = j2 & 1;
                dh[m * 3 + c2] = gbh[m * 16 + ch * 2 + c2];
                dl[m * 3 + c2] = gbl[m * 16 + ch * 2 + c2];
            }
            __syncthreads();
            FragB bh, bl;
            wmma::load_matrix_sync(bh, Hh + ch * 16 * XS + n * 16, XS);
            wmma::load_matrix_sync(bl, Hl + ch * 16 * XS + n * 16, XS);
            #pragma unroll
            for (int j = 0; j < 6; j++) {
                if (val[j]) {
                    FragA ah, al;
                    wmma::load_matrix_sync(ah, sWh + mts[j] * 16 * WS, WS);
                    wmma::load_matrix_sync(al, sWl + mts[j] * 16 * WS, WS);
                    wmma::mma_sync(accb[j], ah, bh, accb[j]);
                    wmma::mma_sync(accb[j], al, bh, accb[j]);
                    wmma::mma_sync(accb[j], ah, bl, accb[j]);
                }
            }
            __syncthreads();
        }
        float* ZB = (float*)(smem + SM_ZB);
        #pragma unroll
        for (int j = 0; j < 6; j++) {
            if (val[j]) {
                int lr = (mts[j] - pass * 12) * 16;
                wmma::store_matrix_sync(ZB + lr * XS + n * 16, accb[j], XS, wmma::mem_row_major);
            }
        }
        __syncthreads();
        int rows = pass ? 176 : 192;
        for (int f = tid; f < rows * 128; f += NTH) {
            int r = f >> 7, t = f & 127;
            int m = pass * 192 + r;
            int tg = t0 + t;
            if (tg >= L) continue;
            float v = ZB[r * XS + t];
            if (m < 240) {
                v += sbv[m];
                size_t o = (size_t)m * L + tg;
                skip[o] = first ? v : skip[o] + v;
            } else if (m < 360 && wres) {
                int rr = m - 240;
                v += rb[rr];
                rout[(size_t)rr * L + tg] = v + rin[(size_t)rr * L + tg];
            }
        }
        __syncthreads();
    }
}

// ---------------- dense head (unchanged SIMT, passing) --------------------------
__global__ __launch_bounds__(NTH, 1)
void dense_kernel(const float* __restrict__ x, const float* __restrict__ dpk,
                  const float* __restrict__ b, float* __restrict__ out,
                  int L, int K, int M, int relu_in, int relu_out) {
    extern __shared__ float sm[];
    float* sX = sm;
    int tid = threadIdx.x;
    int t0 = blockIdx.x * TT;
    for (int idx = tid; idx < K * TT; idx += NTH) {
        int c = idx >> 7, tl0 = idx & 127;
        int t = t0 + tl0;
        float v = (t < L) ? x[c * L + t] : 0.f;
        sX[idx] = relu_in ? fmaxf(v, 0.f) : v;
    }
    __syncthreads();
    const int lid = tid & 31, wid = tid >> 5, tl = 4 * lid;
    const int MP = M / 2;
    #pragma unroll 1
    for (int pass = 0; pass * 64 < MP; pass++) {
        const int k0 = pass * 64 + wid * 4;
        if (k0 >= MP) break;
        const float* drow[4];
        ull z[4][4];
        #pragma unroll
        for (int j = 0; j < 4; j++) {
            int k = k0 + j;
            int kk = k < MP ? k : MP - 1;
            drow[j] = dpk + (size_t)kk * K * 2;
            ull bb = pk2(b[2 * kk], b[2 * kk + 1]);
            z[j][0] = bb; z[j][1] = bb; z[j][2] = bb; z[j][3] = bb;
        }
        {
            ulonglong2 dA[4], dB[4];
            #pragma unroll
            for (int j = 0; j < 4; j++) dA[j] = *(const ulonglong2*)(drow[j]);
            #pragma unroll 1
            for (int c = 0; c < K; c += 4) {
                #pragma unroll
                for (int j = 0; j < 4; j++) dB[j] = *(const ulonglong2*)(drow[j] + 2 * (c + 2));
                halfS(z, sX, c, tl, dA);
                int c4 = (c + 4 < K) ? c + 4 : 0;
                #pragma unroll
                for (int j = 0; j < 4; j++) dA[j] = *(const ulonglong2*)(drow[j] + 2 * c4);
                halfS(z, sX, c + 2, tl, dB);
            }
        }
        int t = t0 + tl;
        #pragma unroll
        for (int j = 0; j < 4; j++) {
            int k = k0 + j;
            if (k >= MP) break;
            float2 v0 = up2(z[j][0]);
            float2 v1 = up2(z[j][1]);
            float2 v2 = up2(z[j][2]);
            float2 v3 = up2(z[j][3]);
            float4 o1 = make_float4(v0.x, v1.x, v2.x, v3.x);
            float4 o2 = make_float4(v0.y, v1.y, v2.y, v3.y);
            if (relu_out) {
                o1.x = fmaxf(o1.x, 0.f); o1.y = fmaxf(o1.y, 0.f);
                o1.z = fmaxf(o1.z, 0.f); o1.w = fmaxf(o1.w, 0.f);
                o2.x = fmaxf(o2.x, 0.f); o2.y = fmaxf(o2.y, 0.f);
                o2.z = fmaxf(o2.z, 0.f); o2.w = fmaxf(o2.w, 0.f);
            }
            float* d1 = &out[(size_t)(2 * k) * L + t];
            float* d2 = &out[(size_t)(2 * k + 1) * L + t];
            if (t + 3 < L) {
                *(float4*)d1 = o1;
                *(float4*)d2 = o2;
            } else {
                float ov1[4] = {o1.x, o1.y, o1.z, o1.w};
                float ov2[4] = {o2.x, o2.y, o2.z, o2.w};
                #pragma unroll
                for (int e = 0; e < 4; e++)
                    if (t + e < L) { d1[e] = ov1[e]; d2[e] = ov2[e]; }
            }
        }
    }
}

// ---------------- host launch ---------------------------------------------------
extern "C" void kernel_launch(void* const* d_in, const int* in_sizes, int n_in,
                              void* d_out, int out_size) {
    const float* wav  = (const float*)d_in[0];
    const float* mel  = (const float*)d_in[1];
    const float* up_w = (const float*)d_in[2];
    const float* up_b = (const float*)d_in[3];
    const float* in_w = (const float*)d_in[4];
    const float* in_b = (const float*)d_in[5];
    const float* bcw  = (const float*)d_in[6];
    const float* bcb  = (const float*)d_in[7];
    const float* bqw  = (const float*)d_in[8];
    const float* bqb  = (const float*)d_in[9];
    const float* bsw  = (const float*)d_in[10];
    const float* bsb  = (const float*)d_in[11];
    const float* brw  = (const float*)d_in[12];
    const float* brb  = (const float*)d_in[13];
    const float* h1w  = (const float*)d_in[14];
    const float* h1b  = (const float*)d_in[15];
    const float* h2w  = (const float*)d_in[16];
    const float* h2b  = (const float*)d_in[17];
    float* out = (float*)d_out;

    int wav_len = in_sizes[0];
    int Tmel = in_sizes[1] / NMEL;
    int up_len = (Tmel - 1) * HOP + 1;
    int pad = KUP - 1 - (KUP + 4 * HOP - 1024);   // = -1
    int cond_len = up_len + 2 * pad - KUP + 1;
    int L = wav_len < cond_len ? wav_len : cond_len;
    if (L > MAXL) L = MAXL;

    float *cond, *res0, *res1, *skip, *yb;
    float2 *dpk1, *dpk2;
    __nv_bfloat16 *wAh, *wAl, *wBh, *wBl;
    cudaGetSymbolAddress((void**)&cond, g_cond);
    cudaGetSymbolAddress((void**)&res0, g_res0);
    cudaGetSymbolAddress((void**)&res1, g_res1);
    cudaGetSymbolAddress((void**)&skip, g_skip);
    cudaGetSymbolAddress((void**)&yb,   g_y);
    cudaGetSymbolAddress((void**)&dpk1, g_dpk1);
    cudaGetSymbolAddress((void**)&dpk2, g_dpk2);
    cudaGetSymbolAddress((void**)&wAh,  g_wAh);
    cudaGetSymbolAddress((void**)&wAl,  g_wAl);
    cudaGetSymbolAddress((void**)&wBh,  g_wBh);
    cudaGetSymbolAddress((void**)&wBl,  g_wBl);

    int condSm = (NMEL * (Tmel + 8) + NMEL * NMEL * 4) * 4;
    int d1Sm   = SC * TT * 4;
    int d2Sm   = NQ * TT * 4;

    cudaFuncSetAttribute(cond_kernel,  cudaFuncAttributeMaxDynamicSharedMemorySize, condSm);
    cudaFuncSetAttribute(block_wmma,   cudaFuncAttributeMaxDynamicSharedMemorySize, SMEM_BLK);
    cudaFuncSetAttribute(dense_kernel, cudaFuncAttributeMaxDynamicSharedMemorySize, d2Sm);

    int nT = (L + TT - 1) / TT;

    int pkTot = NB * 240 * 320 + NB * 368 * 128;
    prepack_wmma<<<(pkTot + 255) / 256, 256>>>(bcw, bqw, bsw, brw, wAh, wAl, wBh, wBl);
    prepack_dense<<<(128 * 240 + 128 * 256 + 255) / 256, 256>>>(h1w, h2w, dpk1, dpk2);
    cond_kernel<<<HOP, 256, condSm>>>(mel, up_w, up_b, cond, L, Tmel);
    init_kernel<<<(RC * L + 255) / 256, 256>>>(wav, in_w, in_b, res0, L);

    const int dils[NB] = {1, 2, 4, 8, 16, 32, 64, 128, 1, 2, 4, 8, 16, 32, 64, 128};
    for (int i = 0; i < NB; i++) {
        const float* rin = (i & 1) ? res1 : res0;
        float* rout = (i & 1) ? res0 : res1;
        block_wmma<<<nT, NTH, SMEM_BLK>>>(rin, rout, skip, cond,
                                          wAh + (size_t)i * 240 * 320,
                                          wAl + (size_t)i * 240 * 320,
                                          wBh + (size_t)i * 368 * 128,
                                          wBl + (size_t)i * 368 * 128,
                                          bcb + i * SC, bqb + i * SC,
                                          bsb + i * SC, brb + i * RC,
                                          dils[i], L, (i == 0) ? 1 : 0, (i != NB - 1) ? 1 : 0);
    }

    dense_kernel<<<nT, NTH, d1Sm>>>(skip, (const float*)dpk1, h1b, yb, L, SC, NQ, 1, 1);
    dense_kernel<<<nT, NTH, d2Sm>>>(yb, (const float*)dpk2, h2b, out, L, NQ, NQ, 0, 0);
    (void)n_in; (void)out_size;
}